// round 14
// baseline (speedup 1.0000x reference)
#include <cuda_runtime.h>
#include <cuda_bf16.h>
#include <cstdint>
#include <math.h>

#define BB 2
#define SS 2048
#define NH 16
#define DH 64
#define HID 1024
#define HALF 256
#define SCALE 0.125f
#define MTOT 4096

#define OUT_ELEMS  (BB*SS*HID)
#define ATTN_ELEMS ((size_t)BB*NH*SS*SS)
#define ZROWS      32768            /* rows per GEMM share (half of 65536) */
#define ZSLOT      448              /* max zero-float4 slots per row */
#define ZTOT       (ZROWS*ZSLOT)    /* 14680064 */

/* ---------------- scratch ---------------- */
__device__ __nv_bfloat16 g_xh[MTOT*HID];
__device__ __nv_bfloat16 g_xl[MTOT*HID];
__device__ __nv_bfloat16 g_wh[4][HID*HID];
__device__ __nv_bfloat16 g_wl[4][HID*HID];
__device__ __nv_bfloat16 g_qh[BB*NH*SS*DH];
__device__ __nv_bfloat16 g_ql[BB*NH*SS*DH];
__device__ __nv_bfloat16 g_kh[BB*NH*SS*DH];
__device__ __nv_bfloat16 g_kl[BB*NH*SS*DH];
__device__ __nv_bfloat16 g_vh[BB*NH*SS*DH];
__device__ __nv_bfloat16 g_vl[BB*NH*SS*DH];

/* ---------------- helpers ---------------- */
__device__ __forceinline__ uint32_t smem_u32(const void* p) {
    uint32_t a;
    asm("{ .reg .u64 t; cvta.to.shared.u64 t, %1; cvt.u32.u64 %0, t; }" : "=r"(a) : "l"(p));
    return a;
}
#define CP_ASYNC16(dst, src) asm volatile("cp.async.cg.shared.global [%0], [%1], 16;" :: "r"(dst), "l"(src))
#define CP_COMMIT()          asm volatile("cp.async.commit_group;" ::: "memory")
#define CP_WAIT1()           asm volatile("cp.async.wait_group 1;" ::: "memory")
#define CP_WAIT0()           asm volatile("cp.async.wait_group 0;" ::: "memory")

#define LDMX4(r0,r1,r2,r3,addr) \
    asm volatile("ldmatrix.sync.aligned.m8n8.x4.shared.b16 {%0,%1,%2,%3}, [%4];" \
        : "=r"(r0), "=r"(r1), "=r"(r2), "=r"(r3) : "r"(addr))
#define LDMX4T(r0,r1,r2,r3,addr) \
    asm volatile("ldmatrix.sync.aligned.m8n8.x4.trans.shared.b16 {%0,%1,%2,%3}, [%4];" \
        : "=r"(r0), "=r"(r1), "=r"(r2), "=r"(r3) : "r"(addr))

#define MMA16816(c, a, b) \
    asm volatile("mma.sync.aligned.m16n8k16.row.col.f32.bf16.bf16.f32 " \
        "{%0,%1,%2,%3}, {%4,%5,%6,%7}, {%8,%9}, {%0,%1,%2,%3};" \
        : "+f"((c)[0]), "+f"((c)[1]), "+f"((c)[2]), "+f"((c)[3]) \
        : "r"((a)[0]), "r"((a)[1]), "r"((a)[2]), "r"((a)[3]), "r"((b)[0]), "r"((b)[1]))

__device__ __forceinline__ void split2(float x, float y, __nv_bfloat162& hi, __nv_bfloat162& lo) {
    __nv_bfloat16 h0 = __float2bfloat16(x), h1 = __float2bfloat16(y);
    lo = __nv_bfloat162(__float2bfloat16(x - __bfloat162float(h0)),
                        __float2bfloat16(y - __bfloat162float(h1)));
    hi = __nv_bfloat162(h0, h1);
}

/* ---------------- fused fp32 -> bf16 hi/lo split ---------------- */
__global__ void split_multi(const float4* __restrict__ X,
                            const float4* __restrict__ W0, const float4* __restrict__ W1,
                            const float4* __restrict__ W2, const float4* __restrict__ W3,
                            __nv_bfloat162* __restrict__ xh, __nv_bfloat162* __restrict__ xl,
                            __nv_bfloat162* __restrict__ wh, __nv_bfloat162* __restrict__ wl)
{
    int r = blockIdx.y;
    const float4* src;
    __nv_bfloat162 *hi, *lo;
    int n4;
    if (r == 0) { src = X; hi = xh; lo = xl; n4 = MTOT * HID / 4; }
    else {
        src = (r == 1) ? W0 : (r == 2) ? W1 : (r == 3) ? W2 : W3;
        hi = wh + (size_t)(r - 1) * (HID * HID / 2);
        lo = wl + (size_t)(r - 1) * (HID * HID / 2);
        n4 = HID * HID / 4;
    }
    for (int i = blockIdx.x * blockDim.x + threadIdx.x; i < n4; i += gridDim.x * blockDim.x) {
        float4 x = src[i];
        __nv_bfloat162 h0, l0, h1, l1;
        split2(x.x, x.y, h0, l0);
        split2(x.z, x.w, h1, l1);
        hi[2*i] = h0; hi[2*i+1] = h1;
        lo[2*i] = l0; lo[2*i+1] = l1;
    }
}

/* ---------------- mma.sync split GEMM, SW128-swizzled smem, 3-stage ----------------
 * Zero-fill: each GEMM zeroes the OUTSIDE-BAND part of its share of the attn
 * tensor (ZROWS rows starting at zrow0), interleaved with compute. The band
 * itself is written by attn_kernel, so the two regions are disjoint and order
 * doesn't matter. */
extern __shared__ char dyn_smem[];

#define GT_TILE  8192
#define GT_STAGE 32768

__device__ __forceinline__ uint32_t sw_phys(uint32_t r, uint32_t colb) {
    uint32_t rowlin = ((r >> 1) << 7) + ((r & 1) << 6);
    return (rowlin + colb) ^ ((rowlin >> 3) & 0x70);
}

template<int MODE, int ZV>
__global__ __launch_bounds__(256, 2)
void mma_gemm(const __nv_bfloat16* __restrict__ Ah, const __nv_bfloat16* __restrict__ Al,
              const __nv_bfloat16* __restrict__ Bh, const __nv_bfloat16* __restrict__ Bl,
              float* __restrict__ Y,
              __nv_bfloat16* __restrict__ qh, __nv_bfloat16* __restrict__ ql,
              __nv_bfloat16* __restrict__ kh, __nv_bfloat16* __restrict__ kl,
              __nv_bfloat16* __restrict__ vh, __nv_bfloat16* __restrict__ vl,
              float* __restrict__ zptr, int zrow0)
{
    uint32_t sb = smem_u32(dyn_smem);
    int tid = threadIdx.x, warp = tid >> 5, lane = tid & 31;
    int warpM = warp >> 2, warpN = warp & 3;
    int bm = blockIdx.y * 128, bn = blockIdx.x * 128;
    int cta = blockIdx.y * gridDim.x + blockIdx.x;
    int ncta = gridDim.x * gridDim.y;

    float acc[4][4][4];
#pragma unroll
    for (int i = 0; i < 4; i++)
#pragma unroll
        for (int j = 0; j < 4; j++)
#pragma unroll
            for (int t = 0; t < 4; t++) acc[i][j][t] = 0.f;

    const __nv_bfloat16* srcs[4] = {Ah, Al, Bh, Bl};

    auto issue_stage = [&](int s, int k0) {
        uint32_t base = sb + s * GT_STAGE;
#pragma unroll
        for (int v = 0; v < 8; v++) {
            int idx = tid + v * 256;
            int t = idx >> 9;
            uint32_t r = (idx >> 2) & 127, seg = idx & 3;
            int rbase = (t < 2) ? bm : bn;
            const __nv_bfloat16* src = srcs[t] + (size_t)(rbase + r) * 1024 + k0 + seg * 8;
            uint32_t dst = base + t * GT_TILE + sw_phys(r, seg * 16);
            CP_ASYNC16(dst, src);
        }
        CP_COMMIT();
    };

    uint32_t aOff[4][2], bOff[2][2];
#pragma unroll
    for (int mt = 0; mt < 4; mt++) {
        uint32_t R = warpM * 64 + mt * 16 + (lane & 7) + ((lane >> 3) & 1) * 8;
#pragma unroll
        for (int ks = 0; ks < 2; ks++)
            aOff[mt][ks] = sw_phys(R, (lane >> 4) * 16 + ks * 32);
    }
#pragma unroll
    for (int j = 0; j < 2; j++) {
        uint32_t R = warpN * 32 + j * 16 + (lane & 7) + ((lane >> 4) & 1) * 8;
#pragma unroll
        for (int ks = 0; ks < 2; ks++)
            bOff[j][ks] = sw_phys(R, ((lane >> 3) & 1) * 16 + ks * 32);
    }

    issue_stage(0, 0);
    issue_stage(1, 32);

    int stg = 0;
    for (int it = 0; it < 32; it++) {
        if (it == 31) CP_WAIT0(); else CP_WAIT1();
        __syncthreads();
        if (it + 2 < 32) {
            int s2 = stg + 2; if (s2 >= 3) s2 -= 3;
            issue_stage(s2, (it + 2) * 32);
        }
        /* overlapped outside-band zero-fill of this GEMM's attn share */
        if (zptr) {
#pragma unroll
            for (int v = 0; v < ZV; v++) {
                int sg = ((it * ZV + v) * ncta + cta) * 256 + tid;
                if (sg < ZTOT) {
                    int row = sg / ZSLOT;
                    int s   = sg - row * ZSLOT;
                    int i   = row & (SS - 1);
                    int L4  = (i > HALF) ? ((i - HALF) >> 2) : 0;
                    int r04 = (i + HALF + 4) >> 2;
                    int col4 = (s < L4) ? s : (r04 + s - L4);
                    if (col4 < SS / 4) {
                        float* p = zptr + ((size_t)(zrow0 + row) * SS + col4 * 4);
                        asm volatile("st.global.cs.v4.f32 [%0], {%1,%1,%1,%1};"
                                     :: "l"(p), "f"(0.f) : "memory");
                    }
                }
            }
        }
        uint32_t st = sb + stg * GT_STAGE;

#pragma unroll
        for (int ks = 0; ks < 2; ks++) {
            uint32_t aH[4][4], aL[4][4], bb[4][2];
#pragma unroll
            for (int mt = 0; mt < 4; mt++)
                LDMX4(aH[mt][0], aH[mt][1], aH[mt][2], aH[mt][3], st + aOff[mt][ks]);
            LDMX4(bb[0][0], bb[0][1], bb[1][0], bb[1][1], st + 2 * GT_TILE + bOff[0][ks]);
            LDMX4(bb[2][0], bb[2][1], bb[3][0], bb[3][1], st + 2 * GT_TILE + bOff[1][ks]);
#pragma unroll
            for (int mt = 0; mt < 4; mt++)
#pragma unroll
                for (int nt = 0; nt < 4; nt++)
                    MMA16816(acc[mt][nt], aH[mt], bb[nt]);
#pragma unroll
            for (int mt = 0; mt < 4; mt++)
                LDMX4(aL[mt][0], aL[mt][1], aL[mt][2], aL[mt][3], st + GT_TILE + aOff[mt][ks]);
#pragma unroll
            for (int mt = 0; mt < 4; mt++)
#pragma unroll
                for (int nt = 0; nt < 4; nt++)
                    MMA16816(acc[mt][nt], aL[mt], bb[nt]);
            LDMX4(bb[0][0], bb[0][1], bb[1][0], bb[1][1], st + 3 * GT_TILE + bOff[0][ks]);
            LDMX4(bb[2][0], bb[2][1], bb[3][0], bb[3][1], st + 3 * GT_TILE + bOff[1][ks]);
#pragma unroll
            for (int mt = 0; mt < 4; mt++)
#pragma unroll
                for (int nt = 0; nt < 4; nt++)
                    MMA16816(acc[mt][nt], aH[mt], bb[nt]);
        }
        if (++stg == 3) stg = 0;
    }

    int row0 = lane >> 2, col0 = (lane & 3) * 2;
    __nv_bfloat16 *Yh = nullptr, *Yl = nullptr;
    int nbase = 0;
    if (MODE == 0) {
        int mat = blockIdx.x >> 3;
        Yh = (mat == 0) ? qh : ((mat == 1) ? kh : vh);
        Yl = (mat == 0) ? ql : ((mat == 1) ? kl : vl);
        nbase = (blockIdx.x & 7) * 128;
    }
#pragma unroll
    for (int mt = 0; mt < 4; mt++) {
#pragma unroll
        for (int half = 0; half < 2; half++) {
            int m = bm + warpM * 64 + mt * 16 + row0 + half * 8;
            int b = m >> 11, s = m & 2047;
#pragma unroll
            for (int nt = 0; nt < 4; nt++) {
                float x0 = acc[mt][nt][half * 2 + 0];
                float x1 = acc[mt][nt][half * 2 + 1];
                if (MODE == 0) {
                    int n = nbase + warpN * 32 + nt * 8 + col0;
                    int h = n >> 6, d0 = n & 63;
                    size_t idx = (((size_t)b * NH + h) * SS + s) * DH + d0;
                    __nv_bfloat162 hi, lo;
                    split2(x0, x1, hi, lo);
                    *(__nv_bfloat162*)(Yh + idx) = hi;
                    *(__nv_bfloat162*)(Yl + idx) = lo;
                } else {
                    int n = bn + warpN * 32 + nt * 8 + col0;
                    float2 v2; v2.x = x0; v2.y = x1;
                    *(float2*)(Y + (size_t)m * HID + n) = v2;
                }
            }
        }
    }
}

/* ---------------- tensor-core sliding-window attention ----------------
 * smem: Sh @0, Sl @35328, Qh @70656, Ql @75264, KV x3 @79872, inv[32] @107520.
 */
#define WW 544
#define SSTR 552
#define OSH 0u
#define OSL 35328u
#define OQH 70656u
#define OQL 75264u
#define OKV 79872u
#define OINV 107520u
#define ATTN_SMEM 107648

__global__ __launch_bounds__(256, 2)
void attn_kernel(float* __restrict__ attn_out, int write_attn)
{
    char* sm = dyn_smem;
    uint32_t sb = smem_u32(sm);
    int tid = threadIdx.x, warp = tid >> 5, lane = tid & 31;
    int bh = blockIdx.y;
    int i0 = blockIdx.x * 32;
    int b = bh >> 4, h = bh & 15;
    size_t base = (size_t)bh * SS * DH;
    const __nv_bfloat16 *Qh = g_qh + base, *Ql = g_ql + base;
    const __nv_bfloat16 *Kh = g_kh + base, *Kl = g_kl + base;
    const __nv_bfloat16 *Vh = g_vh + base, *Vl = g_vl + base;
    int jlo = i0 - HALF;

    /* load Q hi/lo tile: 32x64 */
    {
        int row = tid >> 3, seg = tid & 7;
        uint4 vh4 = *(const uint4*)(Qh + (size_t)(i0 + row) * DH + seg * 8);
        uint4 vl4 = *(const uint4*)(Ql + (size_t)(i0 + row) * DH + seg * 8);
        *(uint4*)(sm + OQH + row * 144 + seg * 16) = vh4;
        *(uint4*)(sm + OQL + row * 144 + seg * 16) = vl4;
    }

    auto load_chunk = [&](const __nv_bfloat16* Mh, const __nv_bfloat16* Ml, int c, int buf) {
#pragma unroll
        for (int u = 0; u < 2; u++) {
            int idx = tid + u * 256;
            int hl = idx >> 8, r = (idx >> 3) & 31, seg = idx & 7;
            int j = jlo + c * 32 + r;
            j = (j < 0) ? 0 : ((j > SS - 1) ? SS - 1 : j);
            const __nv_bfloat16* src = (hl ? Ml : Mh) + (size_t)j * DH + seg * 8;
            uint32_t dst = sb + OKV + buf * 9216 + hl * 4608 + r * 144 + seg * 16;
            CP_ASYNC16(dst, src);
        }
        CP_COMMIT();
    };

    /* ---------- phase 1: scores ---------- */
    {
        int mt = warp >> 2, nt = warp & 3;
        uint32_t aoffQ = (uint32_t)((mt * 16 + (lane & 15)) * 144 + (lane >> 4) * 16);
        uint32_t boffK4 = (uint32_t)((nt * 8 + (lane & 7)) * 144 + ((lane >> 3) & 3) * 16);

        load_chunk(Kh, Kl, 0, 0);
        load_chunk(Kh, Kl, 1, 1);
        __syncthreads();

        uint32_t qHf[4][4], qLf[4][4];
#pragma unroll
        for (int ks = 0; ks < 4; ks++) {
            LDMX4(qHf[ks][0], qHf[ks][1], qHf[ks][2], qHf[ks][3], sb + OQH + aoffQ + ks * 32);
            LDMX4(qLf[ks][0], qLf[ks][1], qLf[ks][2], qLf[ks][3], sb + OQL + aoffQ + ks * 32);
        }

        for (int c = 0; c < 17; c++) {
            if (c == 16) CP_WAIT0(); else CP_WAIT1();
            __syncthreads();
            if (c + 2 < 17) load_chunk(Kh, Kl, c + 2, (c + 2) % 3);
            uint32_t kb = sb + OKV + (c % 3) * 9216;
            float acc[4] = {0.f, 0.f, 0.f, 0.f};
            uint32_t bHf[4][2], bLf[4][2];
            LDMX4(bHf[0][0], bHf[0][1], bHf[1][0], bHf[1][1], kb + boffK4);
            LDMX4(bHf[2][0], bHf[2][1], bHf[3][0], bHf[3][1], kb + boffK4 + 64);
            LDMX4(bLf[0][0], bLf[0][1], bLf[1][0], bLf[1][1], kb + 4608 + boffK4);
            LDMX4(bLf[2][0], bLf[2][1], bLf[3][0], bLf[3][1], kb + 4608 + boffK4 + 64);
#pragma unroll
            for (int ks = 0; ks < 4; ks++) {
                MMA16816(acc, qHf[ks], bHf[ks]);
                MMA16816(acc, qLf[ks], bHf[ks]);
                MMA16816(acc, qHf[ks], bLf[ks]);
            }
            int colb = c * 32 + nt * 8 + (lane & 3) * 2;
#pragma unroll
            for (int half = 0; half < 2; half++) {
                int r = mt * 16 + (lane >> 2) + half * 8;
                int i = i0 + r;
                int j0 = jlo + colb, j1 = j0 + 1;
                float s0 = acc[half * 2 + 0] * SCALE;
                float s1 = acc[half * 2 + 1] * SCALE;
                if (!((j0 >= 0) && (j0 < SS) && (j0 >= i - HALF) && (j0 <= i + HALF))) s0 = -1e30f;
                if (!((j1 >= 0) && (j1 < SS) && (j1 >= i - HALF) && (j1 <= i + HALF))) s1 = -1e30f;
                __nv_bfloat162 hi, lo;
                split2(s0, s1, hi, lo);
                *(__nv_bfloat162*)(sm + OSH + (r * SSTR + colb) * 2) = hi;
                *(__nv_bfloat162*)(sm + OSL + (r * SSTR + colb) * 2) = lo;
            }
        }
        __syncthreads();
    }

    /* prefetch first two V chunks so softmax hides the load latency */
    load_chunk(Vh, Vl, 0, 0);
    load_chunk(Vh, Vl, 1, 1);

    /* ---------- phase 2: softmax, 2-pass, deferred normalization ---------- */
    {
        for (int rr = 0; rr < 4; rr++) {
            int r = warp * 4 + rr;
            uint32_t rh = OSH + r * SSTR * 2, rl = OSL + r * SSTR * 2;
            float mx = -1e30f;
            for (int pc = lane; pc < 272; pc += 32) {
                __nv_bfloat162 hh = *(__nv_bfloat162*)(sm + rh + pc * 4);
                __nv_bfloat162 ll = *(__nv_bfloat162*)(sm + rl + pc * 4);
                float s0 = __bfloat162float(hh.x) + __bfloat162float(ll.x);
                float s1 = __bfloat162float(hh.y) + __bfloat162float(ll.y);
                mx = fmaxf(mx, fmaxf(s0, s1));
            }
#pragma unroll
            for (int o = 16; o > 0; o >>= 1) mx = fmaxf(mx, __shfl_xor_sync(0xffffffffu, mx, o));
            float sum = 0.f;
            for (int pc = lane; pc < 272; pc += 32) {
                __nv_bfloat162 hh = *(__nv_bfloat162*)(sm + rh + pc * 4);
                __nv_bfloat162 ll = *(__nv_bfloat162*)(sm + rl + pc * 4);
                float s0 = __bfloat162float(hh.x) + __bfloat162float(ll.x);
                float s1 = __bfloat162float(hh.y) + __bfloat162float(ll.y);
                float e0 = __expf(s0 - mx);
                float e1 = __expf(s1 - mx);
                sum += e0 + e1;
                __nv_bfloat162 hi, lo;
                split2(e0, e1, hi, lo);
                *(__nv_bfloat162*)(sm + rh + pc * 4) = hi;
                *(__nv_bfloat162*)(sm + rl + pc * 4) = lo;
            }
#pragma unroll
            for (int o = 16; o > 0; o >>= 1) sum += __shfl_xor_sync(0xffffffffu, sum, o);
            if (lane == 0) ((float*)(sm + OINV))[r] = 1.f / sum;
            /* zero-pad S cols 544..551 (read by boundary float4s in write phase) */
            if (lane < 4) {
                *(uint32_t*)(sm + rh + (272 + lane) * 4) = 0;
                *(uint32_t*)(sm + rl + (272 + lane) * 4) = 0;
            }
        }
        __syncthreads();
    }

    /* ---------- phase 2.5: write attn band only (outside zeroed by GEMMs) ---------- */
    if (write_attn) {
        for (int rr = 0; rr < 4; rr++) {
            int r = warp * 4 + rr;
            int i = i0 + r;
            float inv = ((float*)(sm + OINV))[r];
            float* row = attn_out + ((size_t)bh * SS + i) * SS;
            uint32_t rh = OSH + r * SSTR * 2, rl = OSL + r * SSTR * 2;
            int jstart = i - HALF; if (jstart < 0) jstart = 0; jstart &= ~3;
            int jend = i + HALF + 1; if (jend > SS) jend = SS;
            for (int j4 = jstart + lane * 4; j4 < jend; j4 += 128) {
                int cidx = j4 - jlo;   /* multiple of 4, in [0, 544) */
                uint2 uh = *(uint2*)(sm + rh + cidx * 2);
                uint2 ul = *(uint2*)(sm + rl + cidx * 2);
                __nv_bfloat162 h0 = *(__nv_bfloat162*)&uh.x;
                __nv_bfloat162 h1 = *(__nv_bfloat162*)&uh.y;
                __nv_bfloat162 l0 = *(__nv_bfloat162*)&ul.x;
                __nv_bfloat162 l1 = *(__nv_bfloat162*)&ul.y;
                float4 v4;
                v4.x = (__bfloat162float(h0.x) + __bfloat162float(l0.x)) * inv;
                v4.y = (__bfloat162float(h0.y) + __bfloat162float(l0.y)) * inv;
                v4.z = (__bfloat162float(h1.x) + __bfloat162float(l1.x)) * inv;
                v4.w = (__bfloat162float(h1.y) + __bfloat162float(l1.y)) * inv;
                *(float4*)(row + j4) = v4;
            }
        }
    }

    /* ---------- phase 3: PV (on unnormalized E; scale at epilogue) ---------- */
    {
        int mtp = warp >> 2;
        int ntb = (warp & 3) * 2;
        float oacc[2][4];
#pragma unroll
        for (int p = 0; p < 2; p++)
#pragma unroll
            for (int t = 0; t < 4; t++) oacc[p][t] = 0.f;

        uint32_t aoffP = (uint32_t)((mtp * 16 + (lane & 15)) * SSTR * 2 + (lane >> 4) * 16);
        uint32_t vrow4 = (uint32_t)((((lane & 7) + ((lane >> 3) & 1) * 8)) * 144 + (lane >> 4) * 16);

        for (int c = 0; c < 17; c++) {
            if (c == 16) CP_WAIT0(); else CP_WAIT1();
            __syncthreads();
            if (c + 2 < 17) load_chunk(Vh, Vl, c + 2, (c + 2) % 3);
            uint32_t vb = sb + OKV + (c % 3) * 9216;
#pragma unroll
            for (int ks = 0; ks < 2; ks++) {
                uint32_t aH[4], aL[4];
                LDMX4(aH[0], aH[1], aH[2], aH[3], sb + OSH + aoffP + (c * 32 + ks * 16) * 2);
                LDMX4(aL[0], aL[1], aL[2], aL[3], sb + OSL + aoffP + (c * 32 + ks * 16) * 2);
                uint32_t bHf[2][2], bLf[2][2];
                uint32_t va = vb + vrow4 + ks * 16 * 144 + ntb * 16;
                LDMX4T(bHf[0][0], bHf[0][1], bHf[1][0], bHf[1][1], va);
                LDMX4T(bLf[0][0], bLf[0][1], bLf[1][0], bLf[1][1], va + 4608);
#pragma unroll
                for (int p = 0; p < 2; p++) {
                    MMA16816(oacc[p], aH, bHf[p]);
                    MMA16816(oacc[p], aL, bHf[p]);
                    MMA16816(oacc[p], aH, bLf[p]);
                }
            }
        }

        int row0 = lane >> 2, col0 = (lane & 3) * 2;
        float invA = ((float*)(sm + OINV))[mtp * 16 + row0];
        float invB = ((float*)(sm + OINV))[mtp * 16 + row0 + 8];
#pragma unroll
        for (int p = 0; p < 2; p++) {
            int nt = ntb + p;
#pragma unroll
            for (int half = 0; half < 2; half++) {
                float inv = half ? invB : invA;
                int i = i0 + mtp * 16 + row0 + half * 8;
                size_t m = (size_t)b * SS + i;
                int d = nt * 8 + col0;
                float x0 = oacc[p][half * 2 + 0] * inv;
                float x1 = oacc[p][half * 2 + 1] * inv;
                __nv_bfloat162 hi, lo;
                split2(x0, x1, hi, lo);
                size_t idx = m * HID + h * DH + d;
                *(__nv_bfloat162*)(g_xh + idx) = hi;
                *(__nv_bfloat162*)(g_xl + idx) = lo;
            }
        }
    }
}

/* ---------------- launch ---------------- */
extern "C" void kernel_launch(void* const* d_in, const int* in_sizes, int n_in,
                              void* d_out, int out_size)
{
    const float* X = (const float*)d_in[0];
    const float* W[4] = {(const float*)d_in[1], (const float*)d_in[2],
                         (const float*)d_in[3], (const float*)d_in[4]};
    float* out = (float*)d_out;

    __nv_bfloat16 *xh, *xl, *wh, *wl, *qh, *ql, *kh, *kl, *vh, *vl;
    cudaGetSymbolAddress((void**)&xh, g_xh);
    cudaGetSymbolAddress((void**)&xl, g_xl);
    cudaGetSymbolAddress((void**)&wh, g_wh);
    cudaGetSymbolAddress((void**)&wl, g_wl);
    cudaGetSymbolAddress((void**)&qh, g_qh);
    cudaGetSymbolAddress((void**)&ql, g_ql);
    cudaGetSymbolAddress((void**)&kh, g_kh);
    cudaGetSymbolAddress((void**)&kl, g_kl);
    cudaGetSymbolAddress((void**)&vh, g_vh);
    cudaGetSymbolAddress((void**)&vl, g_vl);

    static int attr_set = -1;
    size_t gemm_smem = 3 * GT_STAGE;
    if (attr_set < 0) {
        cudaFuncSetAttribute(attn_kernel, cudaFuncAttributeMaxDynamicSharedMemorySize, ATTN_SMEM);
        cudaFuncSetAttribute(mma_gemm<0, 3>, cudaFuncAttributeMaxDynamicSharedMemorySize, (int)gemm_smem);
        cudaFuncSetAttribute(mma_gemm<1, 7>, cudaFuncAttributeMaxDynamicSharedMemorySize, (int)gemm_smem);
        attr_set = 1;
    }

    int write_attn = ((size_t)out_size >= (size_t)OUT_ELEMS + ATTN_ELEMS) ? 1 : 0;
    float* attn_out = write_attn ? (out + OUT_ELEMS) : out;

    split_multi<<<dim3(512, 5), 256>>>((const float4*)X,
                                       (const float4*)W[0], (const float4*)W[1],
                                       (const float4*)W[2], (const float4*)W[3],
                                       (__nv_bfloat162*)xh, (__nv_bfloat162*)xl,
                                       (__nv_bfloat162*)wh, (__nv_bfloat162*)wl);

    /* fused QKV GEMM (N=3072) + outside-band zero-fill of attn rows [0, 32768) */
    mma_gemm<0, 3><<<dim3(24, 32), 256, gemm_smem>>>(xh, xl, wh, wl, nullptr,
                                                     qh, ql, kh, kl, vh, vl,
                                                     write_attn ? attn_out : nullptr, 0);

    dim3 agrid(SS / 32, BB * NH);
    attn_kernel<<<agrid, 256, ATTN_SMEM>>>(attn_out, write_attn);

    /* out-proj + outside-band zero-fill of attn rows [32768, 65536) —
       disjoint from attn's band writes, so ordering after attn is safe */
    mma_gemm<1, 7><<<dim3(8, 32), 256, gemm_smem>>>(xh, xl,
                                                    wh + (size_t)3 * HID * HID,
                                                    wl + (size_t)3 * HID * HID,
                                                    out, nullptr, nullptr, nullptr, nullptr, nullptr, nullptr,
                                                    write_attn ? attn_out : nullptr, ZROWS);
}

// round 15
// speedup vs baseline: 1.6446x; 1.6446x over previous
#include <cuda_runtime.h>
#include <cuda_bf16.h>
#include <cuda_fp16.h>
#include <cstdint>
#include <math.h>

#define BB 2
#define SS 2048
#define NH 16
#define DH 64
#define HID 1024
#define HALF 256
#define SCALE 0.125f
#define MTOT 4096

#define OUT_ELEMS  (BB*SS*HID)
#define ATTN_ELEMS ((size_t)BB*NH*SS*SS)
#define ATTN_F4    (ATTN_ELEMS/4)

/* ---------------- scratch ---------------- */
__device__ __nv_bfloat16 g_xh[MTOT*HID];
__device__ __nv_bfloat16 g_xl[MTOT*HID];
__device__ __nv_bfloat16 g_wh[4][HID*HID];
__device__ __nv_bfloat16 g_wl[4][HID*HID];
__device__ __nv_bfloat16 g_qh[BB*NH*SS*DH];
__device__ __nv_bfloat16 g_ql[BB*NH*SS*DH];
__device__ __nv_bfloat16 g_kh[BB*NH*SS*DH];
__device__ __nv_bfloat16 g_kl[BB*NH*SS*DH];
__device__ __half        g_vh[BB*NH*SS*DH];   /* V is fp16 hi/lo */
__device__ __half        g_vl[BB*NH*SS*DH];

/* ---------------- helpers ---------------- */
__device__ __forceinline__ uint32_t smem_u32(const void* p) {
    uint32_t a;
    asm("{ .reg .u64 t; cvta.to.shared.u64 t, %1; cvt.u32.u64 %0, t; }" : "=r"(a) : "l"(p));
    return a;
}
#define CP_ASYNC16(dst, src) asm volatile("cp.async.cg.shared.global [%0], [%1], 16;" :: "r"(dst), "l"(src))
#define CP_COMMIT()          asm volatile("cp.async.commit_group;" ::: "memory")
#define CP_WAIT1()           asm volatile("cp.async.wait_group 1;" ::: "memory")
#define CP_WAIT0()           asm volatile("cp.async.wait_group 0;" ::: "memory")

#define LDMX4(r0,r1,r2,r3,addr) \
    asm volatile("ldmatrix.sync.aligned.m8n8.x4.shared.b16 {%0,%1,%2,%3}, [%4];" \
        : "=r"(r0), "=r"(r1), "=r"(r2), "=r"(r3) : "r"(addr))
#define LDMX4T(r0,r1,r2,r3,addr) \
    asm volatile("ldmatrix.sync.aligned.m8n8.x4.trans.shared.b16 {%0,%1,%2,%3}, [%4];" \
        : "=r"(r0), "=r"(r1), "=r"(r2), "=r"(r3) : "r"(addr))

#define MMA16816(c, a, b) \
    asm volatile("mma.sync.aligned.m16n8k16.row.col.f32.bf16.bf16.f32 " \
        "{%0,%1,%2,%3}, {%4,%5,%6,%7}, {%8,%9}, {%0,%1,%2,%3};" \
        : "+f"((c)[0]), "+f"((c)[1]), "+f"((c)[2]), "+f"((c)[3]) \
        : "r"((a)[0]), "r"((a)[1]), "r"((a)[2]), "r"((a)[3]), "r"((b)[0]), "r"((b)[1]))

#define MMAF16(c, a, b) \
    asm volatile("mma.sync.aligned.m16n8k16.row.col.f32.f16.f16.f32 " \
        "{%0,%1,%2,%3}, {%4,%5,%6,%7}, {%8,%9}, {%0,%1,%2,%3};" \
        : "+f"((c)[0]), "+f"((c)[1]), "+f"((c)[2]), "+f"((c)[3]) \
        : "r"((a)[0]), "r"((a)[1]), "r"((a)[2]), "r"((a)[3]), "r"((b)[0]), "r"((b)[1]))

__device__ __forceinline__ void split2(float x, float y, __nv_bfloat162& hi, __nv_bfloat162& lo) {
    __nv_bfloat16 h0 = __float2bfloat16(x), h1 = __float2bfloat16(y);
    lo = __nv_bfloat162(__float2bfloat16(x - __bfloat162float(h0)),
                        __float2bfloat16(y - __bfloat162float(h1)));
    hi = __nv_bfloat162(h0, h1);
}
__device__ __forceinline__ void split2h(float x, float y, __half2& hi, __half2& lo) {
    __half h0 = __float2half_rn(x), h1 = __float2half_rn(y);
    lo = __half2(__float2half_rn(x - __half2float(h0)),
                 __float2half_rn(y - __half2float(h1)));
    hi = __half2(h0, h1);
}

/* ---------------- fused fp32 -> bf16 hi/lo split ---------------- */
__global__ void split_multi(const float4* __restrict__ X,
                            const float4* __restrict__ W0, const float4* __restrict__ W1,
                            const float4* __restrict__ W2, const float4* __restrict__ W3,
                            __nv_bfloat162* __restrict__ xh, __nv_bfloat162* __restrict__ xl,
                            __nv_bfloat162* __restrict__ wh, __nv_bfloat162* __restrict__ wl)
{
    int r = blockIdx.y;
    const float4* src;
    __nv_bfloat162 *hi, *lo;
    int n4;
    if (r == 0) { src = X; hi = xh; lo = xl; n4 = MTOT * HID / 4; }
    else {
        src = (r == 1) ? W0 : (r == 2) ? W1 : (r == 3) ? W2 : W3;
        hi = wh + (size_t)(r - 1) * (HID * HID / 2);
        lo = wl + (size_t)(r - 1) * (HID * HID / 2);
        n4 = HID * HID / 4;
    }
    for (int i = blockIdx.x * blockDim.x + threadIdx.x; i < n4; i += gridDim.x * blockDim.x) {
        float4 x = src[i];
        __nv_bfloat162 h0, l0, h1, l1;
        split2(x.x, x.y, h0, l0);
        split2(x.z, x.w, h1, l1);
        hi[2*i] = h0; hi[2*i+1] = h1;
        lo[2*i] = l0; lo[2*i+1] = l1;
    }
}

/* ---------------- mma.sync split GEMM, SW128-swizzled smem, 3-stage ----------------
 * MODE 0: fused QKV; V is written as fp16 hi/lo, Q/K as bf16 hi/lo. Also streams
 * a linear zero-fill of the attn tensor (R11 scheme, ZV=6). */
extern __shared__ char dyn_smem[];

#define GT_TILE  8192
#define GT_STAGE 32768

__device__ __forceinline__ uint32_t sw_phys(uint32_t r, uint32_t colb) {
    uint32_t rowlin = ((r >> 1) << 7) + ((r & 1) << 6);
    return (rowlin + colb) ^ ((rowlin >> 3) & 0x70);
}

template<int MODE>
__global__ __launch_bounds__(256, 2)
void mma_gemm(const __nv_bfloat16* __restrict__ Ah, const __nv_bfloat16* __restrict__ Al,
              const __nv_bfloat16* __restrict__ Bh, const __nv_bfloat16* __restrict__ Bl,
              float* __restrict__ Y,
              __nv_bfloat16* __restrict__ qh, __nv_bfloat16* __restrict__ ql,
              __nv_bfloat16* __restrict__ kh, __nv_bfloat16* __restrict__ kl,
              __half* __restrict__ vh, __half* __restrict__ vl,
              float* __restrict__ zptr)
{
    uint32_t sb = smem_u32(dyn_smem);
    int tid = threadIdx.x, warp = tid >> 5, lane = tid & 31;
    int warpM = warp >> 2, warpN = warp & 3;
    int bm = blockIdx.y * 128, bn = blockIdx.x * 128;
    int cta = blockIdx.y * gridDim.x + blockIdx.x;

    float acc[4][4][4];
#pragma unroll
    for (int i = 0; i < 4; i++)
#pragma unroll
        for (int j = 0; j < 4; j++)
#pragma unroll
            for (int t = 0; t < 4; t++) acc[i][j][t] = 0.f;

    const __nv_bfloat16* srcs[4] = {Ah, Al, Bh, Bl};

    auto issue_stage = [&](int s, int k0) {
        uint32_t base = sb + s * GT_STAGE;
#pragma unroll
        for (int v = 0; v < 8; v++) {
            int idx = tid + v * 256;
            int t = idx >> 9;
            uint32_t r = (idx >> 2) & 127, seg = idx & 3;
            int rbase = (t < 2) ? bm : bn;
            const __nv_bfloat16* src = srcs[t] + (size_t)(rbase + r) * 1024 + k0 + seg * 8;
            uint32_t dst = base + t * GT_TILE + sw_phys(r, seg * 16);
            CP_ASYNC16(dst, src);
        }
        CP_COMMIT();
    };

    uint32_t aOff[4][2], bOff[2][2];
#pragma unroll
    for (int mt = 0; mt < 4; mt++) {
        uint32_t R = warpM * 64 + mt * 16 + (lane & 7) + ((lane >> 3) & 1) * 8;
#pragma unroll
        for (int ks = 0; ks < 2; ks++)
            aOff[mt][ks] = sw_phys(R, (lane >> 4) * 16 + ks * 32);
    }
#pragma unroll
    for (int j = 0; j < 2; j++) {
        uint32_t R = warpN * 32 + j * 16 + (lane & 7) + ((lane >> 4) & 1) * 8;
#pragma unroll
        for (int ks = 0; ks < 2; ks++)
            bOff[j][ks] = sw_phys(R, ((lane >> 3) & 1) * 16 + ks * 32);
    }

    issue_stage(0, 0);
    issue_stage(1, 32);

    int stg = 0;
    for (int it = 0; it < 32; it++) {
        if (it == 31) CP_WAIT0(); else CP_WAIT1();
        __syncthreads();
        if (it + 2 < 32) {
            int s2 = stg + 2; if (s2 >= 3) s2 -= 3;
            issue_stage(s2, (it + 2) * 32);
        }
        /* linear overlapped zero-fill (R11 scheme) */
        if (MODE == 0 && zptr) {
#pragma unroll
            for (int v = 0; v < 6; v++) {
                size_t g4 = ((size_t)(it * 6 + v) * 768 + cta) * 256 + tid;
                if (g4 < ATTN_F4) {
                    float4* p = (float4*)zptr + g4;
                    asm volatile("st.global.cs.v4.f32 [%0], {%1,%1,%1,%1};"
                                 :: "l"(p), "f"(0.f) : "memory");
                }
            }
        }
        uint32_t st = sb + stg * GT_STAGE;

#pragma unroll
        for (int ks = 0; ks < 2; ks++) {
            uint32_t aH[4][4], aL[4][4], bb[4][2];
#pragma unroll
            for (int mt = 0; mt < 4; mt++)
                LDMX4(aH[mt][0], aH[mt][1], aH[mt][2], aH[mt][3], st + aOff[mt][ks]);
            LDMX4(bb[0][0], bb[0][1], bb[1][0], bb[1][1], st + 2 * GT_TILE + bOff[0][ks]);
            LDMX4(bb[2][0], bb[2][1], bb[3][0], bb[3][1], st + 2 * GT_TILE + bOff[1][ks]);
#pragma unroll
            for (int mt = 0; mt < 4; mt++)
#pragma unroll
                for (int nt = 0; nt < 4; nt++)
                    MMA16816(acc[mt][nt], aH[mt], bb[nt]);
#pragma unroll
            for (int mt = 0; mt < 4; mt++)
                LDMX4(aL[mt][0], aL[mt][1], aL[mt][2], aL[mt][3], st + GT_TILE + aOff[mt][ks]);
#pragma unroll
            for (int mt = 0; mt < 4; mt++)
#pragma unroll
                for (int nt = 0; nt < 4; nt++)
                    MMA16816(acc[mt][nt], aL[mt], bb[nt]);
            LDMX4(bb[0][0], bb[0][1], bb[1][0], bb[1][1], st + 3 * GT_TILE + bOff[0][ks]);
            LDMX4(bb[2][0], bb[2][1], bb[3][0], bb[3][1], st + 3 * GT_TILE + bOff[1][ks]);
#pragma unroll
            for (int mt = 0; mt < 4; mt++)
#pragma unroll
                for (int nt = 0; nt < 4; nt++)
                    MMA16816(acc[mt][nt], aH[mt], bb[nt]);
        }
        if (++stg == 3) stg = 0;
    }

    int row0 = lane >> 2, col0 = (lane & 3) * 2;
    int mat = 0, nbase = 0;
    if (MODE == 0) { mat = blockIdx.x >> 3; nbase = (blockIdx.x & 7) * 128; }
#pragma unroll
    for (int mt = 0; mt < 4; mt++) {
#pragma unroll
        for (int half = 0; half < 2; half++) {
            int m = bm + warpM * 64 + mt * 16 + row0 + half * 8;
            int b = m >> 11, s = m & 2047;
#pragma unroll
            for (int nt = 0; nt < 4; nt++) {
                float x0 = acc[mt][nt][half * 2 + 0];
                float x1 = acc[mt][nt][half * 2 + 1];
                if (MODE == 0) {
                    int n = nbase + warpN * 32 + nt * 8 + col0;
                    int h = n >> 6, d0 = n & 63;
                    size_t idx = (((size_t)b * NH + h) * SS + s) * DH + d0;
                    if (mat == 2) {
                        __half2 hi, lo;
                        split2h(x0, x1, hi, lo);
                        *(__half2*)(vh + idx) = hi;
                        *(__half2*)(vl + idx) = lo;
                    } else {
                        __nv_bfloat16* Yh = (mat == 0) ? qh : kh;
                        __nv_bfloat16* Yl = (mat == 0) ? ql : kl;
                        __nv_bfloat162 hi, lo;
                        split2(x0, x1, hi, lo);
                        *(__nv_bfloat162*)(Yh + idx) = hi;
                        *(__nv_bfloat162*)(Yl + idx) = lo;
                    }
                } else {
                    int n = bn + warpN * 32 + nt * 8 + col0;
                    float2 v2; v2.x = x0; v2.y = x1;
                    *(float2*)(Y + (size_t)m * HID + n) = v2;
                }
            }
        }
    }
}

/* ---------------- tensor-core sliding-window attention ----------------
 * smem: Sh @0, Sl @35328, Qh @70656, Ql @75264, KV x3 @79872, inv[32] @107520.
 * After softmax Sh holds E as fp16 (single); Sl unused in PV.
 */
#define WW 544
#define SSTR 552
#define OSH 0u
#define OSL 35328u
#define OQH 70656u
#define OQL 75264u
#define OKV 79872u
#define OINV 107520u
#define ATTN_SMEM 107648

__global__ __launch_bounds__(256, 2)
void attn_kernel(float* __restrict__ attn_out, int write_attn)
{
    char* sm = dyn_smem;
    uint32_t sb = smem_u32(sm);
    int tid = threadIdx.x, warp = tid >> 5, lane = tid & 31;
    int bh = blockIdx.y;
    int i0 = blockIdx.x * 32;
    int b = bh >> 4, h = bh & 15;
    size_t base = (size_t)bh * SS * DH;
    const __nv_bfloat16 *Qh = g_qh + base, *Ql = g_ql + base;
    const __nv_bfloat16 *Kh = g_kh + base, *Kl = g_kl + base;
    const __half *Vh = g_vh + base, *Vl = g_vl + base;
    int jlo = i0 - HALF;

    /* load Q hi/lo tile: 32x64 */
    {
        int row = tid >> 3, seg = tid & 7;
        uint4 vh4 = *(const uint4*)(Qh + (size_t)(i0 + row) * DH + seg * 8);
        uint4 vl4 = *(const uint4*)(Ql + (size_t)(i0 + row) * DH + seg * 8);
        *(uint4*)(sm + OQH + row * 144 + seg * 16) = vh4;
        *(uint4*)(sm + OQL + row * 144 + seg * 16) = vl4;
    }

    auto load_chunk_bf = [&](const __nv_bfloat16* Mh, const __nv_bfloat16* Ml, int c, int buf) {
#pragma unroll
        for (int u = 0; u < 2; u++) {
            int idx = tid + u * 256;
            int hl = idx >> 8, r = (idx >> 3) & 31, seg = idx & 7;
            int j = jlo + c * 32 + r;
            j = (j < 0) ? 0 : ((j > SS - 1) ? SS - 1 : j);
            const __nv_bfloat16* src = (hl ? Ml : Mh) + (size_t)j * DH + seg * 8;
            uint32_t dst = sb + OKV + buf * 9216 + hl * 4608 + r * 144 + seg * 16;
            CP_ASYNC16(dst, src);
        }
        CP_COMMIT();
    };
    auto load_chunk_h = [&](const __half* Mh, const __half* Ml, int c, int buf) {
#pragma unroll
        for (int u = 0; u < 2; u++) {
            int idx = tid + u * 256;
            int hl = idx >> 8, r = (idx >> 3) & 31, seg = idx & 7;
            int j = jlo + c * 32 + r;
            j = (j < 0) ? 0 : ((j > SS - 1) ? SS - 1 : j);
            const __half* src = (hl ? Ml : Mh) + (size_t)j * DH + seg * 8;
            uint32_t dst = sb + OKV + buf * 9216 + hl * 4608 + r * 144 + seg * 16;
            CP_ASYNC16(dst, src);
        }
        CP_COMMIT();
    };

    /* ---------- phase 1: scores ---------- */
    {
        int mt = warp >> 2, nt = warp & 3;
        uint32_t aoffQ = (uint32_t)((mt * 16 + (lane & 15)) * 144 + (lane >> 4) * 16);
        uint32_t boffK4 = (uint32_t)((nt * 8 + (lane & 7)) * 144 + ((lane >> 3) & 3) * 16);

        load_chunk_bf(Kh, Kl, 0, 0);
        load_chunk_bf(Kh, Kl, 1, 1);
        __syncthreads();

        uint32_t qHf[4][4], qLf[4][4];
#pragma unroll
        for (int ks = 0; ks < 4; ks++) {
            LDMX4(qHf[ks][0], qHf[ks][1], qHf[ks][2], qHf[ks][3], sb + OQH + aoffQ + ks * 32);
            LDMX4(qLf[ks][0], qLf[ks][1], qLf[ks][2], qLf[ks][3], sb + OQL + aoffQ + ks * 32);
        }

        for (int c = 0; c < 17; c++) {
            if (c == 16) CP_WAIT0(); else CP_WAIT1();
            __syncthreads();
            if (c + 2 < 17) load_chunk_bf(Kh, Kl, c + 2, (c + 2) % 3);
            uint32_t kb = sb + OKV + (c % 3) * 9216;
            float acc[4] = {0.f, 0.f, 0.f, 0.f};
            uint32_t bHf[4][2], bLf[4][2];
            LDMX4(bHf[0][0], bHf[0][1], bHf[1][0], bHf[1][1], kb + boffK4);
            LDMX4(bHf[2][0], bHf[2][1], bHf[3][0], bHf[3][1], kb + boffK4 + 64);
            LDMX4(bLf[0][0], bLf[0][1], bLf[1][0], bLf[1][1], kb + 4608 + boffK4);
            LDMX4(bLf[2][0], bLf[2][1], bLf[3][0], bLf[3][1], kb + 4608 + boffK4 + 64);
#pragma unroll
            for (int ks = 0; ks < 4; ks++) {
                MMA16816(acc, qHf[ks], bHf[ks]);
                MMA16816(acc, qLf[ks], bHf[ks]);
                MMA16816(acc, qHf[ks], bLf[ks]);
            }
            int colb = c * 32 + nt * 8 + (lane & 3) * 2;
#pragma unroll
            for (int half = 0; half < 2; half++) {
                int r = mt * 16 + (lane >> 2) + half * 8;
                int i = i0 + r;
                int j0 = jlo + colb, j1 = j0 + 1;
                float s0 = acc[half * 2 + 0] * SCALE;
                float s1 = acc[half * 2 + 1] * SCALE;
                if (!((j0 >= 0) && (j0 < SS) && (j0 >= i - HALF) && (j0 <= i + HALF))) s0 = -1e30f;
                if (!((j1 >= 0) && (j1 < SS) && (j1 >= i - HALF) && (j1 <= i + HALF))) s1 = -1e30f;
                __nv_bfloat162 hi, lo;
                split2(s0, s1, hi, lo);
                *(__nv_bfloat162*)(sm + OSH + (r * SSTR + colb) * 2) = hi;
                *(__nv_bfloat162*)(sm + OSL + (r * SSTR + colb) * 2) = lo;
            }
        }
        __syncthreads();
    }

    /* prefetch first two V chunks so softmax hides the load latency */
    load_chunk_h(Vh, Vl, 0, 0);
    load_chunk_h(Vh, Vl, 1, 1);

    /* ---------- phase 2: softmax, 2-pass; E stored as single fp16 in Sh ---------- */
    {
        for (int rr = 0; rr < 4; rr++) {
            int r = warp * 4 + rr;
            uint32_t rh = OSH + r * SSTR * 2, rl = OSL + r * SSTR * 2;
            float mx = -1e30f;
            for (int pc = lane; pc < 272; pc += 32) {
                __nv_bfloat162 hh = *(__nv_bfloat162*)(sm + rh + pc * 4);
                __nv_bfloat162 ll = *(__nv_bfloat162*)(sm + rl + pc * 4);
                float s0 = __bfloat162float(hh.x) + __bfloat162float(ll.x);
                float s1 = __bfloat162float(hh.y) + __bfloat162float(ll.y);
                mx = fmaxf(mx, fmaxf(s0, s1));
            }
#pragma unroll
            for (int o = 16; o > 0; o >>= 1) mx = fmaxf(mx, __shfl_xor_sync(0xffffffffu, mx, o));
            float sum = 0.f;
            for (int pc = lane; pc < 272; pc += 32) {
                __nv_bfloat162 hh = *(__nv_bfloat162*)(sm + rh + pc * 4);
                __nv_bfloat162 ll = *(__nv_bfloat162*)(sm + rl + pc * 4);
                float s0 = __bfloat162float(hh.x) + __bfloat162float(ll.x);
                float s1 = __bfloat162float(hh.y) + __bfloat162float(ll.y);
                float e0 = __expf(s0 - mx);
                float e1 = __expf(s1 - mx);
                sum += e0 + e1;
                *(__half2*)(sm + rh + pc * 4) = __floats2half2_rn(e0, e1);
            }
#pragma unroll
            for (int o = 16; o > 0; o >>= 1) sum += __shfl_xor_sync(0xffffffffu, sum, o);
            if (lane == 0) ((float*)(sm + OINV))[r] = 1.f / sum;
            /* zero-pad E cols 544..551 */
            if (lane < 4) *(uint32_t*)(sm + rh + (272 + lane) * 4) = 0;
        }
        __syncthreads();
    }

    /* ---------- phase 2.5: write attn band only (outside zeroed by QKV GEMM) ---------- */
    if (write_attn) {
        for (int rr = 0; rr < 4; rr++) {
            int r = warp * 4 + rr;
            int i = i0 + r;
            float inv = ((float*)(sm + OINV))[r];
            float* row = attn_out + ((size_t)bh * SS + i) * SS;
            uint32_t rh = OSH + r * SSTR * 2;
            int jstart = i - HALF; if (jstart < 0) jstart = 0; jstart &= ~3;
            int jend = i + HALF + 1; if (jend > SS) jend = SS;
            for (int j4 = jstart + lane * 4; j4 < jend; j4 += 128) {
                int cidx = j4 - jlo;
                uint2 uh = *(uint2*)(sm + rh + cidx * 2);
                __half2 p0 = *(__half2*)&uh.x;
                __half2 p1 = *(__half2*)&uh.y;
                float4 v4;
                v4.x = __half2float(p0.x) * inv;
                v4.y = __half2float(p0.y) * inv;
                v4.z = __half2float(p1.x) * inv;
                v4.w = __half2float(p1.y) * inv;
                *(float4*)(row + j4) = v4;
            }
        }
    }

    /* ---------- phase 3: PV with fp16 E and fp16 V hi/lo (2 passes) ---------- */
    {
        int mtp = warp >> 2;
        int ntb = (warp & 3) * 2;
        float oacc[2][4];
#pragma unroll
        for (int p = 0; p < 2; p++)
#pragma unroll
            for (int t = 0; t < 4; t++) oacc[p][t] = 0.f;

        uint32_t aoffP = (uint32_t)((mtp * 16 + (lane & 15)) * SSTR * 2 + (lane >> 4) * 16);
        uint32_t vrow4 = (uint32_t)((((lane & 7) + ((lane >> 3) & 1) * 8)) * 144 + (lane >> 4) * 16);

        for (int c = 0; c < 17; c++) {
            if (c == 16) CP_WAIT0(); else CP_WAIT1();
            __syncthreads();
            if (c + 2 < 17) load_chunk_h(Vh, Vl, c + 2, (c + 2) % 3);
            uint32_t vb = sb + OKV + (c % 3) * 9216;
#pragma unroll
            for (int ks = 0; ks < 2; ks++) {
                uint32_t aE[4];
                LDMX4(aE[0], aE[1], aE[2], aE[3], sb + OSH + aoffP + (c * 32 + ks * 16) * 2);
                uint32_t bHf[2][2], bLf[2][2];
                uint32_t va = vb + vrow4 + ks * 16 * 144 + ntb * 16;
                LDMX4T(bHf[0][0], bHf[0][1], bHf[1][0], bHf[1][1], va);
                LDMX4T(bLf[0][0], bLf[0][1], bLf[1][0], bLf[1][1], va + 4608);
#pragma unroll
                for (int p = 0; p < 2; p++) {
                    MMAF16(oacc[p], aE, bHf[p]);
                    MMAF16(oacc[p], aE, bLf[p]);
                }
            }
        }

        int row0 = lane >> 2, col0 = (lane & 3) * 2;
        float invA = ((float*)(sm + OINV))[mtp * 16 + row0];
        float invB = ((float*)(sm + OINV))[mtp * 16 + row0 + 8];
#pragma unroll
        for (int p = 0; p < 2; p++) {
            int nt = ntb + p;
#pragma unroll
            for (int half = 0; half < 2; half++) {
                float inv = half ? invB : invA;
                int i = i0 + mtp * 16 + row0 + half * 8;
                size_t m = (size_t)b * SS + i;
                int d = nt * 8 + col0;
                float x0 = oacc[p][half * 2 + 0] * inv;
                float x1 = oacc[p][half * 2 + 1] * inv;
                __nv_bfloat162 hi, lo;
                split2(x0, x1, hi, lo);
                size_t idx = m * HID + h * DH + d;
                *(__nv_bfloat162*)(g_xh + idx) = hi;
                *(__nv_bfloat162*)(g_xl + idx) = lo;
            }
        }
    }
}

/* ---------------- launch ---------------- */
extern "C" void kernel_launch(void* const* d_in, const int* in_sizes, int n_in,
                              void* d_out, int out_size)
{
    const float* X = (const float*)d_in[0];
    const float* W[4] = {(const float*)d_in[1], (const float*)d_in[2],
                         (const float*)d_in[3], (const float*)d_in[4]};
    float* out = (float*)d_out;

    __nv_bfloat16 *xh, *xl, *wh, *wl, *qh, *ql, *kh, *kl;
    __half *vh, *vl;
    cudaGetSymbolAddress((void**)&xh, g_xh);
    cudaGetSymbolAddress((void**)&xl, g_xl);
    cudaGetSymbolAddress((void**)&wh, g_wh);
    cudaGetSymbolAddress((void**)&wl, g_wl);
    cudaGetSymbolAddress((void**)&qh, g_qh);
    cudaGetSymbolAddress((void**)&ql, g_ql);
    cudaGetSymbolAddress((void**)&kh, g_kh);
    cudaGetSymbolAddress((void**)&kl, g_kl);
    cudaGetSymbolAddress((void**)&vh, g_vh);
    cudaGetSymbolAddress((void**)&vl, g_vl);

    static int attr_set = -1;
    size_t gemm_smem = 3 * GT_STAGE;
    if (attr_set < 0) {
        cudaFuncSetAttribute(attn_kernel, cudaFuncAttributeMaxDynamicSharedMemorySize, ATTN_SMEM);
        cudaFuncSetAttribute(mma_gemm<0>, cudaFuncAttributeMaxDynamicSharedMemorySize, (int)gemm_smem);
        cudaFuncSetAttribute(mma_gemm<1>, cudaFuncAttributeMaxDynamicSharedMemorySize, (int)gemm_smem);
        attr_set = 1;
    }

    int write_attn = ((size_t)out_size >= (size_t)OUT_ELEMS + ATTN_ELEMS) ? 1 : 0;
    float* attn_out = write_attn ? (out + OUT_ELEMS) : out;

    split_multi<<<dim3(512, 5), 256>>>((const float4*)X,
                                       (const float4*)W[0], (const float4*)W[1],
                                       (const float4*)W[2], (const float4*)W[3],
                                       (__nv_bfloat162*)xh, (__nv_bfloat162*)xl,
                                       (__nv_bfloat162*)wh, (__nv_bfloat162*)wl);

    /* fused QKV GEMM (N=3072) + linear zero-fill of the attn tensor */
    mma_gemm<0><<<dim3(24, 32), 256, gemm_smem>>>(xh, xl, wh, wl, nullptr,
                                                  qh, ql, kh, kl, vh, vl,
                                                  write_attn ? attn_out : nullptr);

    dim3 agrid(SS / 32, BB * NH);
    attn_kernel<<<agrid, 256, ATTN_SMEM>>>(attn_out, write_attn);

    mma_gemm<1><<<dim3(8, 32), 256, gemm_smem>>>(xh, xl,
                                                 wh + (size_t)3 * HID * HID,
                                                 wl + (size_t)3 * HID * HID,
                                                 out, nullptr, nullptr, nullptr, nullptr,
                                                 nullptr, nullptr, nullptr);
}

// round 17
// speedup vs baseline: 1.7418x; 1.0591x over previous
#include <cuda_runtime.h>
#include <cuda_bf16.h>
#include <cuda_fp16.h>
#include <cstdint>
#include <math.h>

#define BB 2
#define SS 2048
#define NH 16
#define DH 64
#define HID 1024
#define HALF 256
#define SCALE 0.125f
#define MTOT 4096

#define OUT_ELEMS  (BB*SS*HID)
#define ATTN_ELEMS ((size_t)BB*NH*SS*SS)
#define ATTN_F4    (ATTN_ELEMS/4)

/* ---------------- scratch ---------------- */
__device__ __nv_bfloat16 g_xh[MTOT*HID];     /* X bf16 hi/lo (for Q,K) */
__device__ __nv_bfloat16 g_xl[MTOT*HID];
__device__ __half        g_x16h[MTOT*HID];   /* X fp16 hi/lo (for V) */
__device__ __half        g_x16l[MTOT*HID];
__device__ __nv_bfloat16 g_wbh[2][HID*HID];  /* Wq, Wk bf16 hi/lo */
__device__ __nv_bfloat16 g_wbl[2][HID*HID];
__device__ __half        g_wv16[HID*HID];    /* Wv fp16 (hi only needed) */
__device__ __half        g_wo16[HID*HID];    /* Wo fp16 */
__device__ __nv_bfloat16 g_qh[BB*NH*SS*DH];
__device__ __nv_bfloat16 g_ql[BB*NH*SS*DH];
__device__ __nv_bfloat16 g_kh[BB*NH*SS*DH];
__device__ __nv_bfloat16 g_kl[BB*NH*SS*DH];
__device__ __half        g_vh[BB*NH*SS*DH];
__device__ __half        g_vl[BB*NH*SS*DH];
__device__ __half        g_c16h[MTOT*HID];   /* ctx fp16 hi/lo */
__device__ __half        g_c16l[MTOT*HID];

/* ---------------- helpers ---------------- */
__device__ __forceinline__ uint32_t smem_u32(const void* p) {
    uint32_t a;
    asm("{ .reg .u64 t; cvta.to.shared.u64 t, %1; cvt.u32.u64 %0, t; }" : "=r"(a) : "l"(p));
    return a;
}
#define CP_ASYNC16(dst, src) asm volatile("cp.async.cg.shared.global [%0], [%1], 16;" :: "r"(dst), "l"(src))
#define CP_COMMIT()          asm volatile("cp.async.commit_group;" ::: "memory")
#define CP_WAIT1()           asm volatile("cp.async.wait_group 1;" ::: "memory")
#define CP_WAIT0()           asm volatile("cp.async.wait_group 0;" ::: "memory")

#define LDMX4(r0,r1,r2,r3,addr) \
    asm volatile("ldmatrix.sync.aligned.m8n8.x4.shared.b16 {%0,%1,%2,%3}, [%4];" \
        : "=r"(r0), "=r"(r1), "=r"(r2), "=r"(r3) : "r"(addr))
#define LDMX4T(r0,r1,r2,r3,addr) \
    asm volatile("ldmatrix.sync.aligned.m8n8.x4.trans.shared.b16 {%0,%1,%2,%3}, [%4];" \
        : "=r"(r0), "=r"(r1), "=r"(r2), "=r"(r3) : "r"(addr))

#define MMA16816(c, a, b) \
    asm volatile("mma.sync.aligned.m16n8k16.row.col.f32.bf16.bf16.f32 " \
        "{%0,%1,%2,%3}, {%4,%5,%6,%7}, {%8,%9}, {%0,%1,%2,%3};" \
        : "+f"((c)[0]), "+f"((c)[1]), "+f"((c)[2]), "+f"((c)[3]) \
        : "r"((a)[0]), "r"((a)[1]), "r"((a)[2]), "r"((a)[3]), "r"((b)[0]), "r"((b)[1]))

#define MMAF16(c, a, b) \
    asm volatile("mma.sync.aligned.m16n8k16.row.col.f32.f16.f16.f32 " \
        "{%0,%1,%2,%3}, {%4,%5,%6,%7}, {%8,%9}, {%0,%1,%2,%3};" \
        : "+f"((c)[0]), "+f"((c)[1]), "+f"((c)[2]), "+f"((c)[3]) \
        : "r"((a)[0]), "r"((a)[1]), "r"((a)[2]), "r"((a)[3]), "r"((b)[0]), "r"((b)[1]))

__device__ __forceinline__ void split2(float x, float y, __nv_bfloat162& hi, __nv_bfloat162& lo) {
    __nv_bfloat16 h0 = __float2bfloat16(x), h1 = __float2bfloat16(y);
    lo = __nv_bfloat162(__float2bfloat16(x - __bfloat162float(h0)),
                        __float2bfloat16(y - __bfloat162float(h1)));
    hi = __nv_bfloat162(h0, h1);
}
__device__ __forceinline__ void split2h(float x, float y, __half2& hi, __half2& lo) {
    __half h0 = __float2half_rn(x), h1 = __float2half_rn(y);
    lo = __half2(__float2half_rn(x - __half2float(h0)),
                 __float2half_rn(y - __half2float(h1)));
    hi = __half2(h0, h1);
}

/* ---------------- fused fp32 -> low-precision splits ---------------- */
__global__ void split_multi(const float4* __restrict__ X,
                            const float4* __restrict__ W0, const float4* __restrict__ W1,
                            const float4* __restrict__ W2, const float4* __restrict__ W3)
{
    int r = blockIdx.y;
    if (r == 0) {
        int n4 = MTOT * HID / 4;
        for (int i = blockIdx.x * blockDim.x + threadIdx.x; i < n4; i += gridDim.x * blockDim.x) {
            float4 x = X[i];
            __nv_bfloat162 h0, l0, h1, l1;
            split2(x.x, x.y, h0, l0);
            split2(x.z, x.w, h1, l1);
            ((__nv_bfloat162*)g_xh)[2*i] = h0; ((__nv_bfloat162*)g_xh)[2*i+1] = h1;
            ((__nv_bfloat162*)g_xl)[2*i] = l0; ((__nv_bfloat162*)g_xl)[2*i+1] = l1;
            __half2 fh0, fl0, fh1, fl1;
            split2h(x.x, x.y, fh0, fl0);
            split2h(x.z, x.w, fh1, fl1);
            ((__half2*)g_x16h)[2*i] = fh0; ((__half2*)g_x16h)[2*i+1] = fh1;
            ((__half2*)g_x16l)[2*i] = fl0; ((__half2*)g_x16l)[2*i+1] = fl1;
        }
    } else if (r <= 2) {
        const float4* src = (r == 1) ? W0 : W1;
        __nv_bfloat162* hi = (__nv_bfloat162*)g_wbh[r-1];
        __nv_bfloat162* lo = (__nv_bfloat162*)g_wbl[r-1];
        int n4 = HID * HID / 4;
        for (int i = blockIdx.x * blockDim.x + threadIdx.x; i < n4; i += gridDim.x * blockDim.x) {
            float4 x = src[i];
            __nv_bfloat162 h0, l0, h1, l1;
            split2(x.x, x.y, h0, l0);
            split2(x.z, x.w, h1, l1);
            hi[2*i] = h0; hi[2*i+1] = h1;
            lo[2*i] = l0; lo[2*i+1] = l1;
        }
    } else {
        const float4* src = (r == 3) ? W2 : W3;
        __half2* dst = (__half2*)((r == 3) ? g_wv16 : g_wo16);
        int n4 = HID * HID / 4;
        for (int i = blockIdx.x * blockDim.x + threadIdx.x; i < n4; i += gridDim.x * blockDim.x) {
            float4 x = src[i];
            dst[2*i]   = __floats2half2_rn(x.x, x.y);
            dst[2*i+1] = __floats2half2_rn(x.z, x.w);
        }
    }
}

/* ---------------- mma.sync GEMM, SW128-swizzled smem, 3-stage ----------------
 * MODE 0 (grid 24x32): fused QKV. mat 0/1 (Q,K): bf16 split 3-pass.
 *   mat 2 (V): fp16 X hi/lo x fp16 Wv, 2 passes == exact X x fp16(Wv).
 *   Also streams linear zero-fill of the attn tensor.
 * MODE 1 (grid 8x32): out-proj: fp16 ctx hi/lo x fp16 Wo, 2 passes. */
extern __shared__ char dyn_smem[];

#define GT_TILE  8192
#define GT_STAGE 32768

__device__ __forceinline__ uint32_t sw_phys(uint32_t r, uint32_t colb) {
    uint32_t rowlin = ((r >> 1) << 7) + ((r & 1) << 6);
    return (rowlin + colb) ^ ((rowlin >> 3) & 0x70);
}

template<int MODE>
__global__ __launch_bounds__(256, 2)
void mma_gemm(float* __restrict__ Y, float* __restrict__ zptr)
{
    uint32_t sb = smem_u32(dyn_smem);
    int tid = threadIdx.x, warp = tid >> 5, lane = tid & 31;
    int warpM = warp >> 2, warpN = warp & 3;
    int bm = blockIdx.y * 128;
    int mat = (MODE == 0) ? (blockIdx.x >> 3) : 0;
    int bnB = (MODE == 0) ? (blockIdx.x & 7) * 128 : blockIdx.x * 128;
    bool f16m = (MODE == 1) || (mat == 2);
    int cta = blockIdx.y * gridDim.x + blockIdx.x;

    /* source selection (all cast to bf16* for identical address math) */
    const __nv_bfloat16 *Asrc[2], *Bsrc[2];
    if (MODE == 1) {
        Asrc[0] = (const __nv_bfloat16*)g_c16h; Asrc[1] = (const __nv_bfloat16*)g_c16l;
        Bsrc[0] = (const __nv_bfloat16*)g_wo16; Bsrc[1] = (const __nv_bfloat16*)g_wo16;
    } else if (mat == 2) {
        Asrc[0] = (const __nv_bfloat16*)g_x16h; Asrc[1] = (const __nv_bfloat16*)g_x16l;
        Bsrc[0] = (const __nv_bfloat16*)g_wv16; Bsrc[1] = (const __nv_bfloat16*)g_wv16;
    } else {
        Asrc[0] = g_xh; Asrc[1] = g_xl;
        Bsrc[0] = g_wbh[mat]; Bsrc[1] = g_wbl[mat];
    }

    float acc[4][4][4];
#pragma unroll
    for (int i = 0; i < 4; i++)
#pragma unroll
        for (int j = 0; j < 4; j++)
#pragma unroll
            for (int t = 0; t < 4; t++) acc[i][j][t] = 0.f;

    auto issue_stage = [&](int s, int k0) {
        uint32_t base = sb + s * GT_STAGE;
#pragma unroll
        for (int v = 0; v < 8; v++) {
            int idx = tid + v * 256;
            int t = idx >> 9;
            uint32_t r = (idx >> 2) & 127, seg = idx & 3;
            const __nv_bfloat16* srcm = (t < 2) ? Asrc[t] : Bsrc[t - 2];
            int rbase = (t < 2) ? bm : bnB;
            const __nv_bfloat16* src = srcm + (size_t)(rbase + r) * 1024 + k0 + seg * 8;
            uint32_t dst = base + t * GT_TILE + sw_phys(r, seg * 16);
            CP_ASYNC16(dst, src);
        }
        CP_COMMIT();
    };

    uint32_t aOff[4][2], bOff[2][2];
#pragma unroll
    for (int mt = 0; mt < 4; mt++) {
        uint32_t R = warpM * 64 + mt * 16 + (lane & 7) + ((lane >> 3) & 1) * 8;
#pragma unroll
        for (int ks = 0; ks < 2; ks++)
            aOff[mt][ks] = sw_phys(R, (lane >> 4) * 16 + ks * 32);
    }
#pragma unroll
    for (int j = 0; j < 2; j++) {
        uint32_t R = warpN * 32 + j * 16 + (lane & 7) + ((lane >> 4) & 1) * 8;
#pragma unroll
        for (int ks = 0; ks < 2; ks++)
            bOff[j][ks] = sw_phys(R, ((lane >> 3) & 1) * 16 + ks * 32);
    }

    issue_stage(0, 0);
    issue_stage(1, 32);

    int stg = 0;
    for (int it = 0; it < 32; it++) {
        if (it == 31) CP_WAIT0(); else CP_WAIT1();
        __syncthreads();
        if (it + 2 < 32) {
            int s2 = stg + 2; if (s2 >= 3) s2 -= 3;
            issue_stage(s2, (it + 2) * 32);
        }
        if (MODE == 0 && zptr) {
#pragma unroll
            for (int v = 0; v < 6; v++) {
                size_t g4 = ((size_t)(it * 6 + v) * 768 + cta) * 256 + tid;
                if (g4 < ATTN_F4) {
                    float4* p = (float4*)zptr + g4;
                    asm volatile("st.global.cs.v4.f32 [%0], {%1,%1,%1,%1};"
                                 :: "l"(p), "f"(0.f) : "memory");
                }
            }
        }
        uint32_t st = sb + stg * GT_STAGE;

        if (f16m) {
            /* 2-pass fp16: (Ah + Al) x Bh == exact A x fp16(B) */
#pragma unroll
            for (int ks = 0; ks < 2; ks++) {
                uint32_t aF[4][4], bb[4][2];
                LDMX4(bb[0][0], bb[0][1], bb[1][0], bb[1][1], st + 2 * GT_TILE + bOff[0][ks]);
                LDMX4(bb[2][0], bb[2][1], bb[3][0], bb[3][1], st + 2 * GT_TILE + bOff[1][ks]);
#pragma unroll
                for (int mt = 0; mt < 4; mt++)
                    LDMX4(aF[mt][0], aF[mt][1], aF[mt][2], aF[mt][3], st + aOff[mt][ks]);
#pragma unroll
                for (int mt = 0; mt < 4; mt++)
#pragma unroll
                    for (int nt = 0; nt < 4; nt++)
                        MMAF16(acc[mt][nt], aF[mt], bb[nt]);
#pragma unroll
                for (int mt = 0; mt < 4; mt++)
                    LDMX4(aF[mt][0], aF[mt][1], aF[mt][2], aF[mt][3], st + GT_TILE + aOff[mt][ks]);
#pragma unroll
                for (int mt = 0; mt < 4; mt++)
#pragma unroll
                    for (int nt = 0; nt < 4; nt++)
                        MMAF16(acc[mt][nt], aF[mt], bb[nt]);
            }
        } else {
            /* 3-pass bf16 split */
#pragma unroll
            for (int ks = 0; ks < 2; ks++) {
                uint32_t aH[4][4], aL[4][4], bb[4][2];
#pragma unroll
                for (int mt = 0; mt < 4; mt++)
                    LDMX4(aH[mt][0], aH[mt][1], aH[mt][2], aH[mt][3], st + aOff[mt][ks]);
                LDMX4(bb[0][0], bb[0][1], bb[1][0], bb[1][1], st + 2 * GT_TILE + bOff[0][ks]);
                LDMX4(bb[2][0], bb[2][1], bb[3][0], bb[3][1], st + 2 * GT_TILE + bOff[1][ks]);
#pragma unroll
                for (int mt = 0; mt < 4; mt++)
#pragma unroll
                    for (int nt = 0; nt < 4; nt++)
                        MMA16816(acc[mt][nt], aH[mt], bb[nt]);
#pragma unroll
                for (int mt = 0; mt < 4; mt++)
                    LDMX4(aL[mt][0], aL[mt][1], aL[mt][2], aL[mt][3], st + GT_TILE + aOff[mt][ks]);
#pragma unroll
                for (int mt = 0; mt < 4; mt++)
#pragma unroll
                    for (int nt = 0; nt < 4; nt++)
                        MMA16816(acc[mt][nt], aL[mt], bb[nt]);
                LDMX4(bb[0][0], bb[0][1], bb[1][0], bb[1][1], st + 3 * GT_TILE + bOff[0][ks]);
                LDMX4(bb[2][0], bb[2][1], bb[3][0], bb[3][1], st + 3 * GT_TILE + bOff[1][ks]);
#pragma unroll
                for (int mt = 0; mt < 4; mt++)
#pragma unroll
                    for (int nt = 0; nt < 4; nt++)
                        MMA16816(acc[mt][nt], aH[mt], bb[nt]);
            }
        }
        if (++stg == 3) stg = 0;
    }

    int row0 = lane >> 2, col0 = (lane & 3) * 2;
#pragma unroll
    for (int mt = 0; mt < 4; mt++) {
#pragma unroll
        for (int half = 0; half < 2; half++) {
            int m = bm + warpM * 64 + mt * 16 + row0 + half * 8;
            int b = m >> 11, s = m & 2047;
#pragma unroll
            for (int nt = 0; nt < 4; nt++) {
                float x0 = acc[mt][nt][half * 2 + 0];
                float x1 = acc[mt][nt][half * 2 + 1];
                int n = bnB + warpN * 32 + nt * 8 + col0;
                if (MODE == 0) {
                    int h = n >> 6, d0 = n & 63;
                    size_t idx = (((size_t)b * NH + h) * SS + s) * DH + d0;
                    if (mat == 2) {
                        __half2 hi, lo;
                        split2h(x0, x1, hi, lo);
                        *(__half2*)(g_vh + idx) = hi;
                        *(__half2*)(g_vl + idx) = lo;
                    } else {
                        __nv_bfloat16* Yh = (mat == 0) ? g_qh : g_kh;
                        __nv_bfloat16* Yl = (mat == 0) ? g_ql : g_kl;
                        __nv_bfloat162 hi, lo;
                        split2(x0, x1, hi, lo);
                        *(__nv_bfloat162*)(Yh + idx) = hi;
                        *(__nv_bfloat162*)(Yl + idx) = lo;
                    }
                } else {
                    float2 v2; v2.x = x0; v2.y = x1;
                    *(float2*)(Y + (size_t)m * HID + n) = v2;
                }
            }
        }
    }
}

/* ---------------- tensor-core sliding-window attention ---------------- */
#define WW 544
#define SSTR 552
#define OSH 0u
#define OSL 35328u
#define OQH 70656u
#define OQL 75264u
#define OKV 79872u
#define OINV 107520u
#define ATTN_SMEM 107648

__global__ __launch_bounds__(256, 2)
void attn_kernel(float* __restrict__ attn_out, int write_attn)
{
    char* sm = dyn_smem;
    uint32_t sb = smem_u32(sm);
    int tid = threadIdx.x, warp = tid >> 5, lane = tid & 31;
    int bh = blockIdx.y;
    int i0 = blockIdx.x * 32;
    int b = bh >> 4, h = bh & 15;
    size_t base = (size_t)bh * SS * DH;
    const __nv_bfloat16 *Qh = g_qh + base, *Ql = g_ql + base;
    const __nv_bfloat16 *Kh = g_kh + base, *Kl = g_kl + base;
    const __half *Vh = g_vh + base, *Vl = g_vl + base;
    int jlo = i0 - HALF;

    {
        int row = tid >> 3, seg = tid & 7;
        uint4 vh4 = *(const uint4*)(Qh + (size_t)(i0 + row) * DH + seg * 8);
        uint4 vl4 = *(const uint4*)(Ql + (size_t)(i0 + row) * DH + seg * 8);
        *(uint4*)(sm + OQH + row * 144 + seg * 16) = vh4;
        *(uint4*)(sm + OQL + row * 144 + seg * 16) = vl4;
    }

    auto load_chunk_bf = [&](const __nv_bfloat16* Mh, const __nv_bfloat16* Ml, int c, int buf) {
#pragma unroll
        for (int u = 0; u < 2; u++) {
            int idx = tid + u * 256;
            int hl = idx >> 8, r = (idx >> 3) & 31, seg = idx & 7;
            int j = jlo + c * 32 + r;
            j = (j < 0) ? 0 : ((j > SS - 1) ? SS - 1 : j);
            const __nv_bfloat16* src = (hl ? Ml : Mh) + (size_t)j * DH + seg * 8;
            uint32_t dst = sb + OKV + buf * 9216 + hl * 4608 + r * 144 + seg * 16;
            CP_ASYNC16(dst, src);
        }
        CP_COMMIT();
    };
    auto load_chunk_h = [&](const __half* Mh, const __half* Ml, int c, int buf) {
#pragma unroll
        for (int u = 0; u < 2; u++) {
            int idx = tid + u * 256;
            int hl = idx >> 8, r = (idx >> 3) & 31, seg = idx & 7;
            int j = jlo + c * 32 + r;
            j = (j < 0) ? 0 : ((j > SS - 1) ? SS - 1 : j);
            const __half* src = (hl ? Ml : Mh) + (size_t)j * DH + seg * 8;
            uint32_t dst = sb + OKV + buf * 9216 + hl * 4608 + r * 144 + seg * 16;
            CP_ASYNC16(dst, src);
        }
        CP_COMMIT();
    };

    /* ---------- phase 1: scores (bf16 3-pass) ---------- */
    {
        int mt = warp >> 2, nt = warp & 3;
        uint32_t aoffQ = (uint32_t)((mt * 16 + (lane & 15)) * 144 + (lane >> 4) * 16);
        uint32_t boffK4 = (uint32_t)((nt * 8 + (lane & 7)) * 144 + ((lane >> 3) & 3) * 16);

        load_chunk_bf(Kh, Kl, 0, 0);
        load_chunk_bf(Kh, Kl, 1, 1);
        __syncthreads();

        uint32_t qHf[4][4], qLf[4][4];
#pragma unroll
        for (int ks = 0; ks < 4; ks++) {
            LDMX4(qHf[ks][0], qHf[ks][1], qHf[ks][2], qHf[ks][3], sb + OQH + aoffQ + ks * 32);
            LDMX4(qLf[ks][0], qLf[ks][1], qLf[ks][2], qLf[ks][3], sb + OQL + aoffQ + ks * 32);
        }

        for (int c = 0; c < 17; c++) {
            if (c == 16) CP_WAIT0(); else CP_WAIT1();
            __syncthreads();
            if (c + 2 < 17) load_chunk_bf(Kh, Kl, c + 2, (c + 2) % 3);
            uint32_t kb = sb + OKV + (c % 3) * 9216;
            float acc[4] = {0.f, 0.f, 0.f, 0.f};
            uint32_t bHf[4][2], bLf[4][2];
            LDMX4(bHf[0][0], bHf[0][1], bHf[1][0], bHf[1][1], kb + boffK4);
            LDMX4(bHf[2][0], bHf[2][1], bHf[3][0], bHf[3][1], kb + boffK4 + 64);
            LDMX4(bLf[0][0], bLf[0][1], bLf[1][0], bLf[1][1], kb + 4608 + boffK4);
            LDMX4(bLf[2][0], bLf[2][1], bLf[3][0], bLf[3][1], kb + 4608 + boffK4 + 64);
#pragma unroll
            for (int ks = 0; ks < 4; ks++) {
                MMA16816(acc, qHf[ks], bHf[ks]);
                MMA16816(acc, qLf[ks], bHf[ks]);
                MMA16816(acc, qHf[ks], bLf[ks]);
            }
            int colb = c * 32 + nt * 8 + (lane & 3) * 2;
#pragma unroll
            for (int half = 0; half < 2; half++) {
                int r = mt * 16 + (lane >> 2) + half * 8;
                int i = i0 + r;
                int j0 = jlo + colb, j1 = j0 + 1;
                float s0 = acc[half * 2 + 0] * SCALE;
                float s1 = acc[half * 2 + 1] * SCALE;
                if (!((j0 >= 0) && (j0 < SS) && (j0 >= i - HALF) && (j0 <= i + HALF))) s0 = -1e30f;
                if (!((j1 >= 0) && (j1 < SS) && (j1 >= i - HALF) && (j1 <= i + HALF))) s1 = -1e30f;
                __nv_bfloat162 hi, lo;
                split2(s0, s1, hi, lo);
                *(__nv_bfloat162*)(sm + OSH + (r * SSTR + colb) * 2) = hi;
                *(__nv_bfloat162*)(sm + OSL + (r * SSTR + colb) * 2) = lo;
            }
        }
        __syncthreads();
    }

    load_chunk_h(Vh, Vl, 0, 0);
    load_chunk_h(Vh, Vl, 1, 1);

    /* ---------- phase 2: softmax; E stored as single fp16 in Sh ---------- */
    {
        for (int rr = 0; rr < 4; rr++) {
            int r = warp * 4 + rr;
            uint32_t rh = OSH + r * SSTR * 2, rl = OSL + r * SSTR * 2;
            float mx = -1e30f;
            for (int pc = lane; pc < 272; pc += 32) {
                __nv_bfloat162 hh = *(__nv_bfloat162*)(sm + rh + pc * 4);
                __nv_bfloat162 ll = *(__nv_bfloat162*)(sm + rl + pc * 4);
                float s0 = __bfloat162float(hh.x) + __bfloat162float(ll.x);
                float s1 = __bfloat162float(hh.y) + __bfloat162float(ll.y);
                mx = fmaxf(mx, fmaxf(s0, s1));
            }
#pragma unroll
            for (int o = 16; o > 0; o >>= 1) mx = fmaxf(mx, __shfl_xor_sync(0xffffffffu, mx, o));
            float sum = 0.f;
            for (int pc = lane; pc < 272; pc += 32) {
                __nv_bfloat162 hh = *(__nv_bfloat162*)(sm + rh + pc * 4);
                __nv_bfloat162 ll = *(__nv_bfloat162*)(sm + rl + pc * 4);
                float s0 = __bfloat162float(hh.x) + __bfloat162float(ll.x);
                float s1 = __bfloat162float(hh.y) + __bfloat162float(ll.y);
                float e0 = __expf(s0 - mx);
                float e1 = __expf(s1 - mx);
                sum += e0 + e1;
                *(__half2*)(sm + rh + pc * 4) = __floats2half2_rn(e0, e1);
            }
#pragma unroll
            for (int o = 16; o > 0; o >>= 1) sum += __shfl_xor_sync(0xffffffffu, sum, o);
            if (lane == 0) ((float*)(sm + OINV))[r] = 1.f / sum;
            if (lane < 4) *(uint32_t*)(sm + rh + (272 + lane) * 4) = 0;
        }
        __syncthreads();
    }

    /* ---------- phase 2.5: write attn band only ---------- */
    if (write_attn) {
        for (int rr = 0; rr < 4; rr++) {
            int r = warp * 4 + rr;
            int i = i0 + r;
            float inv = ((float*)(sm + OINV))[r];
            float* row = attn_out + ((size_t)bh * SS + i) * SS;
            uint32_t rh = OSH + r * SSTR * 2;
            int jstart = i - HALF; if (jstart < 0) jstart = 0; jstart &= ~3;
            int jend = i + HALF + 1; if (jend > SS) jend = SS;
            for (int j4 = jstart + lane * 4; j4 < jend; j4 += 128) {
                int cidx = j4 - jlo;
                uint2 uh = *(uint2*)(sm + rh + cidx * 2);
                __half2 p0 = *(__half2*)&uh.x;
                __half2 p1 = *(__half2*)&uh.y;
                float4 v4;
                v4.x = __half2float(p0.x) * inv;
                v4.y = __half2float(p0.y) * inv;
                v4.z = __half2float(p1.x) * inv;
                v4.w = __half2float(p1.y) * inv;
                *(float4*)(row + j4) = v4;
            }
        }
    }

    /* ---------- phase 3: PV (fp16 E x fp16 V hi/lo, 2 passes) ---------- */
    {
        int mtp = warp >> 2;
        int ntb = (warp & 3) * 2;
        float oacc[2][4];
#pragma unroll
        for (int p = 0; p < 2; p++)
#pragma unroll
            for (int t = 0; t < 4; t++) oacc[p][t] = 0.f;

        uint32_t aoffP = (uint32_t)((mtp * 16 + (lane & 15)) * SSTR * 2 + (lane >> 4) * 16);
        uint32_t vrow4 = (uint32_t)((((lane & 7) + ((lane >> 3) & 1) * 8)) * 144 + (lane >> 4) * 16);

        for (int c = 0; c < 17; c++) {
            if (c == 16) CP_WAIT0(); else CP_WAIT1();
            __syncthreads();
            if (c + 2 < 17) load_chunk_h(Vh, Vl, c + 2, (c + 2) % 3);
            uint32_t vb = sb + OKV + (c % 3) * 9216;
#pragma unroll
            for (int ks = 0; ks < 2; ks++) {
                uint32_t aE[4];
                LDMX4(aE[0], aE[1], aE[2], aE[3], sb + OSH + aoffP + (c * 32 + ks * 16) * 2);
                uint32_t bHf[2][2], bLf[2][2];
                uint32_t va = vb + vrow4 + ks * 16 * 144 + ntb * 16;
                LDMX4T(bHf[0][0], bHf[0][1], bHf[1][0], bHf[1][1], va);
                LDMX4T(bLf[0][0], bLf[0][1], bLf[1][0], bLf[1][1], va + 4608);
#pragma unroll
                for (int p = 0; p < 2; p++) {
                    MMAF16(oacc[p], aE, bHf[p]);
                    MMAF16(oacc[p], aE, bLf[p]);
                }
            }
        }

        int row0 = lane >> 2, col0 = (lane & 3) * 2;
        float invA = ((float*)(sm + OINV))[mtp * 16 + row0];
        float invB = ((float*)(sm + OINV))[mtp * 16 + row0 + 8];
#pragma unroll
        for (int p = 0; p < 2; p++) {
            int nt = ntb + p;
#pragma unroll
            for (int half = 0; half < 2; half++) {
                float inv = half ? invB : invA;
                int i = i0 + mtp * 16 + row0 + half * 8;
                size_t m = (size_t)b * SS + i;
                int d = nt * 8 + col0;
                float x0 = oacc[p][half * 2 + 0] * inv;
                float x1 = oacc[p][half * 2 + 1] * inv;
                __half2 hi, lo;
                split2h(x0, x1, hi, lo);
                size_t idx = m * HID + h * DH + d;
                *(__half2*)(g_c16h + idx) = hi;
                *(__half2*)(g_c16l + idx) = lo;
            }
        }
    }
}

/* ---------------- launch ---------------- */
extern "C" void kernel_launch(void* const* d_in, const int* in_sizes, int n_in,
                              void* d_out, int out_size)
{
    const float* X = (const float*)d_in[0];
    const float* W[4] = {(const float*)d_in[1], (const float*)d_in[2],
                         (const float*)d_in[3], (const float*)d_in[4]};
    float* out = (float*)d_out;

    static int attr_set = -1;
    size_t gemm_smem = 3 * GT_STAGE;
    if (attr_set < 0) {
        cudaFuncSetAttribute(attn_kernel, cudaFuncAttributeMaxDynamicSharedMemorySize, ATTN_SMEM);
        cudaFuncSetAttribute(mma_gemm<0>, cudaFuncAttributeMaxDynamicSharedMemorySize, (int)gemm_smem);
        cudaFuncSetAttribute(mma_gemm<1>, cudaFuncAttributeMaxDynamicSharedMemorySize, (int)gemm_smem);
        attr_set = 1;
    }

    int write_attn = ((size_t)out_size >= (size_t)OUT_ELEMS + ATTN_ELEMS) ? 1 : 0;
    float* attn_out = write_attn ? (out + OUT_ELEMS) : out;

    split_multi<<<dim3(512, 5), 256>>>((const float4*)X,
                                       (const float4*)W[0], (const float4*)W[1],
                                       (const float4*)W[2], (const float4*)W[3]);

    /* fused QKV GEMM (Q,K bf16 3-pass; V fp16 2-pass) + attn zero-fill */
    mma_gemm<0><<<dim3(24, 32), 256, gemm_smem>>>(nullptr, write_attn ? attn_out : nullptr);

    dim3 agrid(SS / 32, BB * NH);
    attn_kernel<<<agrid, 256, ATTN_SMEM>>>(attn_out, write_attn);

    /* out-proj: fp16 ctx hi/lo x fp16 Wo, 2-pass */
    mma_gemm<1><<<dim3(8, 32), 256, gemm_smem>>>(out, nullptr);
}